// round 1
// baseline (speedup 1.0000x reference)
#include <cuda_runtime.h>

// Problem: AveragePrecision_4690104287320
// output: (16, 3, 128, 128, 85) f32  -> pred rows of 85 floats
// anchors: (3, 2) f32 (UNUSED by reference)
// targets: (16, 50, 5) f32
// Outputs (tuple, flattened in order):
//   pred_out: (16, 49152, 7) f32  = 5,505,024 floats
//   target_masked: (16, 50, 5)    = 4,000 floats (identity copy; zero rows stay zero)

#define CONF_THRESHOLD 0.25f

__global__ void __launch_bounds__(256)
yolo_fuse_kernel(const float* __restrict__ pred, float* __restrict__ out, int nrows)
{
    const int warp = (blockIdx.x * blockDim.x + threadIdx.x) >> 5;
    const int lane = threadIdx.x & 31;
    if (warp >= nrows) return;

    const float* row = pred + (long long)warp * 85;

    // Lane i covers global indices i, i+32, i+64 (if < 85).
    const float v0 = __ldg(row + lane);
    const float v1 = __ldg(row + lane + 32);
    const bool  has2 = (lane + 64) < 85;           // lanes 0..20
    const float v2 = has2 ? __ldg(row + lane + 64) : -1e30f;

    // Local max/argmax over class scores (global idx >= 5 -> class idx = gidx-5).
    // Candidates in increasing-index order; strict '>' keeps the earliest (jnp.argmax tie rule).
    float best = -1e30f;
    int   bidx = 0x7fffffff;
    if (lane >= 5)            { best = v0; bidx = lane - 5;  }
    if (v1 > best)            { best = v1; bidx = lane + 27; }   // (lane+32)-5
    if (has2 && v2 > best)    { best = v2; bidx = lane + 59; }   // (lane+64)-5

    // Warp butterfly reduction: max value, lowest index on ties.
    #pragma unroll
    for (int off = 16; off; off >>= 1) {
        float ob = __shfl_xor_sync(0xffffffffu, best, off);
        int   oi = __shfl_xor_sync(0xffffffffu, bidx, off);
        if (ob > best || (ob == best && oi < bidx)) { best = ob; bidx = oi; }
    }

    // objectness = pred[4], held in lane 4's v0
    const float obj  = __shfl_sync(0xffffffffu, v0, 4);
    const float conf = best * obj;
    const bool  keep = conf > CONF_THRESHOLD;

    // Lanes 0..6 write the fused row (7 consecutive floats).
    if (lane < 7) {
        float val;
        if (lane < 5)       val = keep ? v0 : 0.0f;           // box_obj[lane]
        else if (lane == 5) val = keep ? (float)bidx : 0.0f;  // cls_id
        else                val = keep ? conf : 0.0f;         // conf
        out[(long long)warp * 7 + lane] = val;
    }
}

// target_masked == targets: rows that are all-zero map to zero anyway,
// and valid rows pass through unchanged. Plain copy.
__global__ void copy_targets_kernel(const float* __restrict__ t, float* __restrict__ out, int n)
{
    int i = blockIdx.x * blockDim.x + threadIdx.x;
    if (i < n) out[i] = t[i];
}

extern "C" void kernel_launch(void* const* d_in, const int* in_sizes, int n_in,
                              void* d_out, int out_size)
{
    const float* output  = (const float*)d_in[0];   // (16,3,128,128,85)
    // d_in[1] = anchors (unused)
    const float* targets = (const float*)d_in[2];   // (16,50,5)

    float* out = (float*)d_out;

    const int V = 85;
    const int nrows = in_sizes[0] / V;              // 786432
    const int ntarg = in_sizes[2];                  // 4000

    // 8 warps (8 rows) per 256-thread block
    const int rows_per_block = 256 / 32;
    const int grid = (nrows + rows_per_block - 1) / rows_per_block;
    yolo_fuse_kernel<<<grid, 256>>>(output, out, nrows);

    float* targ_out = out + (long long)nrows * 7;
    copy_targets_kernel<<<(ntarg + 255) / 256, 256>>>(targets, targ_out, ntarg);
}

// round 2
// speedup vs baseline: 1.7687x; 1.7687x over previous
#include <cuda_runtime.h>

// Problem: AveragePrecision_4690104287320
// output: (16, 3, 128, 128, 85) f32  -> 786,432 rows of 85 floats
// anchors: (3, 2) f32 (UNUSED by reference)
// targets: (16, 50, 5) f32
// Outputs (flattened tuple):
//   pred_out: (16, 49152, 7) f32  = 5,505,024 floats
//   target_masked: identity copy of targets (zero rows stay zero)

#define CONF_THRESHOLD 0.25f

// Block = 128 threads = 128 rows. 128*85 floats staged in smem.
constexpr int ROWS      = 128;
constexpr int VROW      = 85;
constexpr int SMEM_F    = ROWS * VROW;        // 10880 floats = 43,520 B
constexpr int SMEM_V4   = SMEM_F / 4;         // 2720 float4
constexpr int OUT_F     = ROWS * 7;           // 896 floats
constexpr int OUT_V4    = OUT_F / 4;          // 224 float4

__global__ void __launch_bounds__(ROWS)
yolo_fuse_kernel(const float4* __restrict__ pred4, float4* __restrict__ out4)
{
    __shared__ float smem[SMEM_F];

    const int tid = threadIdx.x;
    const long long blk = blockIdx.x;

    // ---- Stage 128 rows into smem with coalesced float4 streaming loads ----
    const float4* src = pred4 + blk * SMEM_V4;
    float4* s4 = reinterpret_cast<float4*>(smem);
    #pragma unroll
    for (int i = 0; i < (SMEM_V4 + ROWS - 1) / ROWS; i++) {
        int idx = tid + i * ROWS;
        if (idx < SMEM_V4) s4[idx] = __ldcs(src + idx);
    }
    __syncthreads();

    // ---- Thread-per-row scan (stride 85 floats: bank-conflict-free) ----
    const float* row = smem + tid * VROW;
    const float b0 = row[0], b1 = row[1], b2 = row[2], b3 = row[3];
    const float obj = row[4];

    // 4 interleaved argmax chains over the 80 class scores (row[5..84]).
    // Within a chain indices increase, strict '>' keeps the earliest.
    float m0 = row[5], m1 = row[6], m2 = row[7], m3 = row[8];
    int   i0 = 0,      i1 = 1,      i2 = 2,      i3 = 3;
    #pragma unroll
    for (int k = 1; k < 20; k++) {
        const float v0 = row[5 + 4 * k];
        const float v1 = row[6 + 4 * k];
        const float v2 = row[7 + 4 * k];
        const float v3 = row[8 + 4 * k];
        if (v0 > m0) { m0 = v0; i0 = 4 * k;     }
        if (v1 > m1) { m1 = v1; i1 = 4 * k + 1; }
        if (v2 > m2) { m2 = v2; i2 = 4 * k + 2; }
        if (v3 > m3) { m3 = v3; i3 = 4 * k + 3; }
    }
    // Merge chains: higher value wins; on exact tie, lower index (jnp.argmax).
    float best = m0; int bidx = i0;
    if (m1 > best || (m1 == best && i1 < bidx)) { best = m1; bidx = i1; }
    if (m2 > best || (m2 == best && i2 < bidx)) { best = m2; bidx = i2; }
    if (m3 > best || (m3 == best && i3 < bidx)) { best = m3; bidx = i3; }

    const float conf = best * obj;
    const bool  keep = conf > CONF_THRESHOLD;

    float r[7];
    r[0] = keep ? b0 : 0.0f;
    r[1] = keep ? b1 : 0.0f;
    r[2] = keep ? b2 : 0.0f;
    r[3] = keep ? b3 : 0.0f;
    r[4] = keep ? obj : 0.0f;
    r[5] = keep ? (float)bidx : 0.0f;
    r[6] = keep ? conf : 0.0f;

    // ---- Stage results through smem (stride-7: conflict-free), store coalesced ----
    __syncthreads();   // all reads of row data done before overwrite
    #pragma unroll
    for (int j = 0; j < 7; j++) smem[tid * 7 + j] = r[j];
    __syncthreads();

    float4* dst = out4 + blk * OUT_V4;
    #pragma unroll
    for (int i = 0; i < (OUT_V4 + ROWS - 1) / ROWS; i++) {
        int idx = tid + i * ROWS;
        if (idx < OUT_V4) __stcs(dst + idx, s4[idx]);
    }
}

__global__ void copy_targets_kernel(const float* __restrict__ t, float* __restrict__ out, int n)
{
    int i = blockIdx.x * blockDim.x + threadIdx.x;
    if (i < n) out[i] = t[i];
}

extern "C" void kernel_launch(void* const* d_in, const int* in_sizes, int n_in,
                              void* d_out, int out_size)
{
    const float* output  = (const float*)d_in[0];   // (16,3,128,128,85)
    // d_in[1] = anchors (unused)
    const float* targets = (const float*)d_in[2];   // (16,50,5)

    float* out = (float*)d_out;

    const int nrows = in_sizes[0] / VROW;           // 786432 (multiple of 128)
    const int ntarg = in_sizes[2];                  // 4000

    const int grid = nrows / ROWS;                  // 6144 blocks
    yolo_fuse_kernel<<<grid, ROWS>>>((const float4*)output, (float4*)out);

    float* targ_out = out + (long long)nrows * 7;
    copy_targets_kernel<<<(ntarg + 255) / 256, 256>>>(targets, targ_out, ntarg);
}

// round 3
// speedup vs baseline: 2.2087x; 1.2488x over previous
#include <cuda_runtime.h>
#include <cstdint>

// Problem: AveragePrecision_4690104287320
// output: (16, 3, 128, 128, 85) f32  -> 786,432 rows of 85 floats
// anchors: unused. targets: (16,50,5) f32 -> identity copy.
// Out: pred_out (786432 x 7 f32) then target copy (4000 f32).

#define CONF_THRESHOLD 0.25f

constexpr int ROWS    = 128;
constexpr int VROW    = 85;
constexpr int SMEM_F  = ROWS * VROW;        // 10880 floats
constexpr int TILE_B  = SMEM_F * 4;         // 43520 bytes (16B multiple)
constexpr int OUT_F   = ROWS * 7;           // 896 floats
constexpr int OUT_V4  = OUT_F / 4;          // 224 float4

__device__ __forceinline__ uint32_t smem_u32(const void* p) {
    uint32_t a;
    asm("{ .reg .u64 t; cvta.to.shared.u64 t, %1; cvt.u32.u64 %0, t; }" : "=r"(a) : "l"(p));
    return a;
}

__global__ void __launch_bounds__(ROWS)
yolo_fuse_kernel(const float* __restrict__ pred,
                 float4* __restrict__ out4,
                 const float4* __restrict__ targ4,
                 float4* __restrict__ targ_out4)
{
    __shared__ __align__(16) float smem[SMEM_F];
    __shared__ __align__(8) uint64_t mbar;

    const int tid = threadIdx.x;
    const long long blk = blockIdx.x;
    const uint32_t mb = smem_u32(&mbar);

    // ---- mbarrier init ----
    if (tid == 0) {
        asm volatile("mbarrier.init.shared.b64 [%0], %1;" :: "r"(mb), "r"(1) : "memory");
    }
    __syncthreads();

    // ---- bulk async copy: 43,520 B global -> shared (single DMA) ----
    if (tid == 0) {
        asm volatile("mbarrier.arrive.expect_tx.shared.b64 _, [%0], %1;"
                     :: "r"(mb), "r"((uint32_t)TILE_B) : "memory");
        const float* src = pred + blk * (long long)SMEM_F;
        asm volatile("cp.async.bulk.shared::cta.global.mbarrier::complete_tx::bytes "
                     "[%0], [%1], %2, [%3];"
                     :: "r"(smem_u32(smem)), "l"(src), "r"((uint32_t)TILE_B), "r"(mb)
                     : "memory");
    }

    // ---- fused targets copy (first 8 blocks, 125 float4 each = 4000 floats) ----
    if (blk < 8 && tid < 125) {
        int idx = (int)blk * 125 + tid;
        targ_out4[idx] = targ4[idx];
    }

    // ---- wait for tile ----
    {
        uint32_t done;
        asm volatile(
            "{\n\t.reg .pred p;\n\t"
            "mbarrier.try_wait.parity.acquire.cta.shared::cta.b64 p, [%1], %2;\n\t"
            "selp.b32 %0, 1, 0, p;\n\t}"
            : "=r"(done) : "r"(mb), "r"(0) : "memory");
        if (!done) {
            asm volatile(
                "{\n\t.reg .pred P1;\n\t"
                "WAIT_LOOP_%=:\n\t"
                "mbarrier.try_wait.parity.acquire.cta.shared::cta.b64 P1, [%0], %1, 0x989680;\n\t"
                "@P1 bra.uni WAIT_DONE_%=;\n\t"
                "bra.uni WAIT_LOOP_%=;\n\t"
                "WAIT_DONE_%=:\n\t}"
                :: "r"(mb), "r"(0) : "memory");
        }
    }

    // ---- thread-per-row scan (stride-85 floats: conflict-free) ----
    const float* row = smem + tid * VROW;
    const float b0 = row[0], b1 = row[1], b2 = row[2], b3 = row[3];
    const float obj = row[4];

    float m0 = row[5], m1 = row[6], m2 = row[7], m3 = row[8];
    int   i0 = 0,      i1 = 1,      i2 = 2,      i3 = 3;
    #pragma unroll
    for (int k = 1; k < 20; k++) {
        const float v0 = row[5 + 4 * k];
        const float v1 = row[6 + 4 * k];
        const float v2 = row[7 + 4 * k];
        const float v3 = row[8 + 4 * k];
        if (v0 > m0) { m0 = v0; i0 = 4 * k;     }
        if (v1 > m1) { m1 = v1; i1 = 4 * k + 1; }
        if (v2 > m2) { m2 = v2; i2 = 4 * k + 2; }
        if (v3 > m3) { m3 = v3; i3 = 4 * k + 3; }
    }
    float best = m0; int bidx = i0;
    if (m1 > best || (m1 == best && i1 < bidx)) { best = m1; bidx = i1; }
    if (m2 > best || (m2 == best && i2 < bidx)) { best = m2; bidx = i2; }
    if (m3 > best || (m3 == best && i3 < bidx)) { best = m3; bidx = i3; }

    const float conf = best * obj;
    const bool  keep = conf > CONF_THRESHOLD;

    float r[7];
    r[0] = keep ? b0 : 0.0f;
    r[1] = keep ? b1 : 0.0f;
    r[2] = keep ? b2 : 0.0f;
    r[3] = keep ? b3 : 0.0f;
    r[4] = keep ? obj : 0.0f;
    r[5] = keep ? (float)bidx : 0.0f;
    r[6] = keep ? conf : 0.0f;

    // ---- stage results (stride-7: conflict-free), store coalesced float4 ----
    __syncthreads();
    #pragma unroll
    for (int j = 0; j < 7; j++) smem[tid * 7 + j] = r[j];
    __syncthreads();

    const float4* s4 = reinterpret_cast<const float4*>(smem);
    float4* dst = out4 + blk * OUT_V4;
    #pragma unroll
    for (int i = 0; i < (OUT_V4 + ROWS - 1) / ROWS; i++) {
        int idx = tid + i * ROWS;
        if (idx < OUT_V4) __stcs(dst + idx, s4[idx]);
    }
}

extern "C" void kernel_launch(void* const* d_in, const int* in_sizes, int n_in,
                              void* d_out, int out_size)
{
    const float* output  = (const float*)d_in[0];   // (16,3,128,128,85)
    const float* targets = (const float*)d_in[2];   // (16,50,5)

    float* out = (float*)d_out;

    const int nrows = in_sizes[0] / VROW;           // 786432 (multiple of 128)
    float* targ_out = out + (long long)nrows * 7;

    const int grid = nrows / ROWS;                  // 6144 blocks
    yolo_fuse_kernel<<<grid, ROWS>>>(output, (float4*)out,
                                     (const float4*)targets, (float4*)targ_out);
}